// round 12
// baseline (speedup 1.0000x reference)
#include <cuda_runtime.h>
#include <cstdint>

#define BSZ 4
#define LM  256
#define LE  512
#define HD  512
#define VOC 32000

#define STAGES 3
#define TILEF  2304      // floats per A or B stage buffer (64*36 or 32*72)
#define GSMEM  (STAGES * 2 * TILEF * 4)   // 55296 B dynamic smem per GEMM block

// Scratch (device globals; no allocation allowed in kernel_launch)
__device__ float g_G[HD * HD];               // Wm @ We^T * scale    (1 MB)
__device__ float g_T[BSZ * LM * HD];         // M @ G                (2 MB)
__device__ float g_log[4][BSZ * LM * LE];    // logits K-split partials (8 MB)
__device__ int   g_sidx[BSZ][LE];            // per-batch sorted scatter indices
__device__ int   g_sperm[BSZ][LE];           // original e for each sorted slot

// ---------------------------------------------------------------------------
// Init kernel: blocks 0..3 bitonic-sort batch b's 512 scatter indices
// (keeping the source position as payload); remaining blocks zero G and T.
// ---------------------------------------------------------------------------
__global__ __launch_bounds__(256) void k_init(
    const int* __restrict__ idx, float4* __restrict__ a, long na4,
    float4* __restrict__ b4, long nb4)
{
    if (blockIdx.x < BSZ) {
        __shared__ int keys[LE], vals[LE];
        int b = blockIdx.x, t = threadIdx.x;
#pragma unroll
        for (int rep = 0; rep < 2; rep++) {
            int i = t + rep * 256;
            keys[i] = idx[b * LE + i];
            vals[i] = i;
        }
        __syncthreads();
        for (int k = 2; k <= LE; k <<= 1) {
            for (int j = k >> 1; j > 0; j >>= 1) {
#pragma unroll
                for (int rep = 0; rep < 2; rep++) {
                    int i = t + rep * 256;
                    int p = i ^ j;
                    if (p > i) {
                        bool up = ((i & k) == 0);
                        int ki = keys[i], kp = keys[p];
                        if ((ki > kp) == up) {
                            keys[i] = kp; keys[p] = ki;
                            int vi = vals[i]; vals[i] = vals[p]; vals[p] = vi;
                        }
                    }
                }
                __syncthreads();
            }
        }
#pragma unroll
        for (int rep = 0; rep < 2; rep++) {
            int i = t + rep * 256;
            g_sidx[b][i]  = keys[i];
            g_sperm[b][i] = vals[i];
        }
    } else {
        long base = (long)(blockIdx.x - BSZ) * 256 + threadIdx.x;
        long stride = (long)(gridDim.x - BSZ) * 256;
        float4 z = make_float4(0.f, 0.f, 0.f, 0.f);
        for (long j = base; j < na4; j += stride) a[j] = z;
        for (long j = base; j < nb4; j += stride) b4[j] = z;
    }
}

// ---------------------------------------------------------------------------
// tf32 tensor-core GEMM core: 64x64 tile, 256 threads (4x2 warps of 16x32),
// BK=32, 3-stage cp.async pipeline, mma.sync.m16n8k8.tf32.
// TB=true:  C[m,n] (+)= alpha * sum_k A[m,k] * B[n,k]   (NT, both K-major)
// TB=false: C[m,n] (+)= alpha * sum_k A[m,k] * B[k,n]   (NN)
// ATOMIC=true: accumulate into C with atomicAdd (for K-split partial sums).
// ---------------------------------------------------------------------------
__device__ __forceinline__ void cp16(void* dst, const void* src)
{
    uint32_t d = (uint32_t)__cvta_generic_to_shared(dst);
    asm volatile("cp.async.cg.shared.global [%0], [%1], 16;\n"
                 :: "r"(d), "l"(src));
}
__device__ __forceinline__ void cp_commit()
{
    asm volatile("cp.async.commit_group;\n" ::: "memory");
}
__device__ __forceinline__ void cp_wait0()
{
    asm volatile("cp.async.wait_group 0;\n" ::: "memory");
}
__device__ __forceinline__ void cp_wait1()
{
    asm volatile("cp.async.wait_group 1;\n" ::: "memory");
}
__device__ __forceinline__ void mma_tf32(float* d, const uint32_t* a,
                                         const uint32_t* b)
{
    asm volatile(
        "mma.sync.aligned.m16n8k8.row.col.f32.tf32.tf32.f32 "
        "{%0,%1,%2,%3}, {%4,%5,%6,%7}, {%8,%9}, {%0,%1,%2,%3};\n"
        : "+f"(d[0]), "+f"(d[1]), "+f"(d[2]), "+f"(d[3])
        : "r"(a[0]), "r"(a[1]), "r"(a[2]), "r"(a[3]),
          "r"(b[0]), "r"(b[1]));
}

#define PA 36   // smem pitch, K-major tiles (banks 4*gid+tig: conflict-free)
#define PB 72   // smem pitch, NN B tile     (banks 8*tig+gid: conflict-free)

template <bool TB, bool ATOMIC>
__device__ __forceinline__ void gemm_core(
    const float* __restrict__ A, const float* __restrict__ B,
    float* __restrict__ C, int lda, int ldb, int ldc,
    int m0, int n0, int kOff, int kLen, float alpha, float* smem)
{
    float (*As)[TILEF] = reinterpret_cast<float(*)[TILEF]>(smem);
    float (*Bs)[TILEF] = reinterpret_cast<float(*)[TILEF]>(smem
                                                           + STAGES * TILEF);

    const int tid  = threadIdx.x;
    const int lane = tid & 31, w = tid >> 5;
    const int gid = lane >> 2, tig = lane & 3;
    const int wm = (w & 3) * 16, wn = (w >> 2) * 32;

    const int NK = kLen / 32;

    auto loadA = [&](int st, int kt) {
        int k0 = kOff + kt * 32;
#pragma unroll
        for (int i = 0; i < 2; i++) {
            int id = tid + i * 256;
            int row = id >> 3, cc = id & 7;
            cp16(&As[st][row * PA + cc * 4],
                 A + (long)(m0 + row) * lda + k0 + cc * 4);
        }
    };
    auto loadB = [&](int st, int kt) {
        int k0 = kOff + kt * 32;
        if (TB) {
#pragma unroll
            for (int i = 0; i < 2; i++) {
                int id = tid + i * 256;
                int row = id >> 3, cc = id & 7;
                cp16(&Bs[st][row * PA + cc * 4],
                     B + (long)(n0 + row) * ldb + k0 + cc * 4);
            }
        } else {
#pragma unroll
            for (int i = 0; i < 2; i++) {
                int id = tid + i * 256;
                int row = id >> 4, cc = id & 15;
                cp16(&Bs[st][row * PB + cc * 4],
                     B + (long)(k0 + row) * ldb + n0 + cc * 4);
            }
        }
    };

    float acc[4][4] = {};

    // prologue: 2 stages in flight
    loadA(0, 0); loadB(0, 0); cp_commit();
    if (NK > 1) { loadA(1, 1); loadB(1, 1); cp_commit(); }

    int buf = 0;        // stage being consumed this iter
    int ls  = 2;        // stage the next prefetch writes into
    for (int kt = 0; kt < NK; kt++) {
        if (kt < NK - 1) cp_wait1(); else cp_wait0();
        __syncthreads();
        if (kt + 2 < NK) {
            loadA(ls, kt + 2);
            loadB(ls, kt + 2);
            cp_commit();
            ls = (ls == STAGES - 1) ? 0 : ls + 1;
        }
#pragma unroll
        for (int ks = 0; ks < 4; ks++) {
            const int kk = ks * 8;
            uint32_t a[4];
            {
                int rb = wm + gid;
                a[0] = __float_as_uint(As[buf][(rb)     * PA + kk + tig]);
                a[1] = __float_as_uint(As[buf][(rb + 8) * PA + kk + tig]);
                a[2] = __float_as_uint(As[buf][(rb)     * PA + kk + tig + 4]);
                a[3] = __float_as_uint(As[buf][(rb + 8) * PA + kk + tig + 4]);
            }
            uint32_t b[4][2];
#pragma unroll
            for (int nj = 0; nj < 4; nj++) {
                int cb = wn + nj * 8 + gid;
                if (TB) {
                    b[nj][0] = __float_as_uint(Bs[buf][cb * PA + kk + tig]);
                    b[nj][1] = __float_as_uint(Bs[buf][cb * PA + kk + tig + 4]);
                } else {
                    b[nj][0] = __float_as_uint(Bs[buf][(kk + tig)     * PB + cb]);
                    b[nj][1] = __float_as_uint(Bs[buf][(kk + tig + 4) * PB + cb]);
                }
            }
#pragma unroll
            for (int nj = 0; nj < 4; nj++)
                mma_tf32(acc[nj], a, b[nj]);
        }
        buf = (buf == STAGES - 1) ? 0 : buf + 1;
    }

#pragma unroll
    for (int nj = 0; nj < 4; nj++) {
        int r0 = m0 + wm + gid;
        int c0 = n0 + wn + nj * 8 + 2 * tig;
        if (ATOMIC) {
            atomicAdd(&C[(long)r0 * ldc + c0],           acc[nj][0] * alpha);
            atomicAdd(&C[(long)r0 * ldc + c0 + 1],       acc[nj][1] * alpha);
            atomicAdd(&C[(long)(r0 + 8) * ldc + c0],     acc[nj][2] * alpha);
            atomicAdd(&C[(long)(r0 + 8) * ldc + c0 + 1], acc[nj][3] * alpha);
        } else {
            C[(long)r0 * ldc + c0]           = acc[nj][0] * alpha;
            C[(long)r0 * ldc + c0 + 1]       = acc[nj][1] * alpha;
            C[(long)(r0 + 8) * ldc + c0]     = acc[nj][2] * alpha;
            C[(long)(r0 + 8) * ldc + c0 + 1] = acc[nj][3] * alpha;
        }
    }
}

// ---------------------------------------------------------------------------
// G = Wm @ We^T * scale  (512x512, NT), K-split x4 with atomic accumulation.
// ---------------------------------------------------------------------------
__global__ __launch_bounds__(256) void k_G(
    const float* __restrict__ Wm, const float* __restrict__ We,
    float* __restrict__ G, float scale)
{
    extern __shared__ float smem[];
    gemm_core<true, true>(Wm, We, G, HD, HD, HD,
                          blockIdx.y * 64, blockIdx.x * 64,
                          blockIdx.z * 128, 128, scale, smem);
}

// ---------------------------------------------------------------------------
// T = M_flat @ G  (1024x512, NN), K-split x2 with atomic accumulation.
// ---------------------------------------------------------------------------
__global__ __launch_bounds__(256) void k_T(
    const float* __restrict__ M, const float* __restrict__ G,
    float* __restrict__ T)
{
    extern __shared__ float smem[];
    gemm_core<false, true>(M, G, T, HD, HD, HD,
                           blockIdx.y * 64, blockIdx.x * 64,
                           blockIdx.z * 256, 256, 1.f, smem);
}

// ---------------------------------------------------------------------------
// logits[b] = T[b] @ E[b]^T (NT), K-split x4 into 4 separate partial buffers.
// grid = (8, 4, 16): z = b*4 + h.
// ---------------------------------------------------------------------------
__global__ __launch_bounds__(256) void k_log(
    const float* __restrict__ T, const float* __restrict__ E,
    float* __restrict__ logs)
{
    extern __shared__ float smem[];
    int z = blockIdx.z;
    int b = z >> 2, h = z & 3;
    const float* A = T + (long)b * LM * HD;
    const float* B = E + (long)b * LE * HD;
    float* C = logs + (long)h * BSZ * LM * LE + (long)b * LM * LE;
    gemm_core<true, false>(A, B, C, HD, HD, LE,
                           blockIdx.y * 64, blockIdx.x * 64,
                           h * 128, 128, 1.f, smem);
}

// ---------------------------------------------------------------------------
// Block reduction for 512 threads (16 warps). red16 is a 16-float smem array.
// ---------------------------------------------------------------------------
__device__ __forceinline__ float bred512(float v, bool mx, float* red16,
                                         int lane, int w)
{
#pragma unroll
    for (int o = 16; o > 0; o >>= 1) {
        float u = __shfl_xor_sync(0xffffffffu, v, o);
        v = mx ? fmaxf(v, u) : v + u;
    }
    if (lane == 0) red16[w] = v;
    __syncthreads();
    float x = red16[lane & 15];
#pragma unroll
    for (int o = 8; o > 0; o >>= 1) {
        float u = __shfl_xor_sync(0xffffffffu, x, o);
        x = mx ? fmaxf(x, u) : x + u;
    }
    __syncthreads();   // red16 free for next use
    return x;          // identical in every thread
}

// ---------------------------------------------------------------------------
// Fused output kernel, one block per row (1024 blocks, 512 threads, ~6 KB
// smem). Uses the per-batch SORTED index list: compute lambda + dual softmax,
// permute weights into sorted order, then each thread composes its 64
// contiguous output floats in registers (zeros + merged weights from its
// sorted run) and streams them to GMEM. No 64 KB smem row, no readback pass.
// ---------------------------------------------------------------------------
__global__ __launch_bounds__(512) void k_scatter(
    const float* __restrict__ bq, const float* __restrict__ bc,
    const float* __restrict__ D, const float* __restrict__ Cq,
    const float* __restrict__ Cc, const float* __restrict__ Wl,
    const float* __restrict__ bl, const float* __restrict__ logs,
    float* __restrict__ out)
{
    __shared__ float wgt[LE];     // weight by original position e
    __shared__ float ws[LE];      // weight by sorted slot
    __shared__ int   sidx[LE];    // sorted vocab indices
    __shared__ float red16[16];

    const int r = blockIdx.x;                // 0 .. BSZ*LM-1
    const int b = r >> 8;                    // r / LM
    const int t = threadIdx.x, lane = t & 31, w = t >> 5;

    // lambda (512 threads x 1 element each of the 3 concatenated chunks)
    const float* dr  = D  + (long)r * HD;
    const float* cqr = Cq + (long)r * HD;
    const float* ccr = Cc + (long)r * HD;
    float s = dr[t] * Wl[t] + cqr[t] * Wl[HD + t] + ccr[t] * Wl[2 * HD + t];
    s = bred512(s, false, red16, lane, w);
    float lam = 1.f / (1.f + __expf(-(s + bl[0])));

    // logits: one element per thread (LE == 512), sum of 4 K-split partials
    const long rl = (long)r * LE + t;
    const long str = (long)BSZ * LM * LE;
    float l = logs[rl] + logs[str + rl] + logs[2 * str + rl] + logs[3 * str + rl];
    float vq = l + bq[b * LE + t];
    float vc = l + bc[b * LE + t];

    float mq = bred512(vq, true, red16, lane, w);
    float mc = bred512(vc, true, red16, lane, w);
    float eq = __expf(vq - mq);
    float ec = __expf(vc - mc);
    float sq = bred512(eq, false, red16, lane, w);
    float sc = bred512(ec, false, red16, lane, w);

    wgt[t] = lam * eq / sq + (1.f - lam) * ec / sc;
    int si = g_sidx[b][t];
    int sp = g_sperm[b][t];
    sidx[t] = si;
    __syncthreads();
    ws[t] = wgt[sp];
    __syncthreads();

    // each thread composes output floats [t*64, t*64+64) in registers
    const int base = t * 64;
    float4* o4 = (float4*)(out + (long)r * VOC);

    // lower_bound(sidx, base)
    int lo = 0, hi = LE;
    while (lo < hi) {
        int mid = (lo + hi) >> 1;
        if (sidx[mid] < base) lo = mid + 1; else hi = mid;
    }
    int ptr = lo;

#pragma unroll 4
    for (int k = 0; k < 16; k++) {
        int g = base + k * 4;
        if (g >= VOC) break;
        float4 f = make_float4(0.f, 0.f, 0.f, 0.f);
        while (ptr < LE && sidx[ptr] < g + 4) {
            int d = sidx[ptr] - g;
            float v = ws[ptr];
            if (d == 0) f.x += v;
            else if (d == 1) f.y += v;
            else if (d == 2) f.z += v;
            else f.w += v;
            ptr++;
        }
        __stcs(o4 + (g >> 2), f);
    }
}

// ---------------------------------------------------------------------------
extern "C" void kernel_launch(void* const* d_in, const int* in_sizes, int n_in,
                              void* d_out, int out_size)
{
    const int*   inputs = (const int*)  d_in[0];
    const float* D      = (const float*)d_in[1];
    const float* Cq     = (const float*)d_in[2];
    const float* Cc     = (const float*)d_in[3];
    const float* Mi     = (const float*)d_in[4];
    const float* E      = (const float*)d_in[5];
    const float* bq     = (const float*)d_in[6];
    const float* bc     = (const float*)d_in[7];
    const float* Wl     = (const float*)d_in[8];
    const float* bl     = (const float*)d_in[9];
    const float* We     = (const float*)d_in[10];
    const float* Wm     = (const float*)d_in[11];
    float* out = (float*)d_out;

    float *gG, *gT, *gL;
    cudaGetSymbolAddress((void**)&gG, g_G);
    cudaGetSymbolAddress((void**)&gT, g_T);
    cudaGetSymbolAddress((void**)&gL, g_log);

    static bool init = false;
    if (!init) {
        cudaFuncSetAttribute(k_G,
                             cudaFuncAttributeMaxDynamicSharedMemorySize,
                             GSMEM);
        cudaFuncSetAttribute(k_T,
                             cudaFuncAttributeMaxDynamicSharedMemorySize,
                             GSMEM);
        cudaFuncSetAttribute(k_log,
                             cudaFuncAttributeMaxDynamicSharedMemorySize,
                             GSMEM);
        init = true;
    }

    const float scale = 0.044194173824159216f;  // 512^-0.5

    // init: sort per-batch scatter indices (4 blocks) + zero G/T accumulators
    k_init<<<196, 256>>>(inputs, (float4*)gG, HD * HD / 4,
                         (float4*)gT, (long)BSZ * LM * HD / 4);
    // G = Wm @ We^T * scale   (K-split x4, atomic epilogue, 256 blocks)
    k_G<<<dim3(8, 8, 4), 256, GSMEM>>>(Wm, We, gG, scale);
    // T = M_flat @ G          (K-split x2, atomic epilogue, 256 blocks)
    k_T<<<dim3(8, 16, 2), 256, GSMEM>>>(Mi, gG, gT);
    // logits partials         (K-split x4 into 4 buffers, 512 blocks)
    k_log<<<dim3(8, 4, 16), 256, GSMEM>>>(gT, E, gL);
    // fused lambda + softmax + register-composed scatter + streamed write
    k_scatter<<<BSZ * LM, 512>>>(bq, bc, D, Cq, Cc, Wl, bl, gL, out);
}

// round 13
// speedup vs baseline: 1.7673x; 1.7673x over previous
#include <cuda_runtime.h>
#include <cstdint>

#define BSZ 4
#define LM  256
#define LE  512
#define HD  512
#define VOC 32000
#define NSPAN 250        // VOC / 128 output spans per row

#define STAGES 3
#define TILEF  2304      // floats per A or B stage buffer (64*36 or 32*72)
#define GSMEM  (STAGES * 2 * TILEF * 4)   // 55296 B dynamic smem per GEMM block

// Scratch (device globals; no allocation allowed in kernel_launch)
__device__ float g_G[HD * HD];               // Wm @ We^T * scale    (1 MB)
__device__ float g_T[BSZ * LM * HD];         // M @ G                (2 MB)
__device__ float g_log[4][BSZ * LM * LE];    // logits K-split partials (8 MB)
__device__ int   g_sidx[BSZ][LE];            // per-batch sorted scatter indices
__device__ int   g_sperm[BSZ][LE];           // original e for each sorted slot

// ---------------------------------------------------------------------------
// Init kernel: blocks 0..3 bitonic-sort batch b's 512 scatter indices
// (keeping the source position as payload); remaining blocks zero G and T.
// ---------------------------------------------------------------------------
__global__ __launch_bounds__(256) void k_init(
    const int* __restrict__ idx, float4* __restrict__ a, long na4,
    float4* __restrict__ b4, long nb4)
{
    if (blockIdx.x < BSZ) {
        __shared__ int keys[LE], vals[LE];
        int b = blockIdx.x, t = threadIdx.x;
#pragma unroll
        for (int rep = 0; rep < 2; rep++) {
            int i = t + rep * 256;
            keys[i] = idx[b * LE + i];
            vals[i] = i;
        }
        __syncthreads();
        for (int k = 2; k <= LE; k <<= 1) {
            for (int j = k >> 1; j > 0; j >>= 1) {
#pragma unroll
                for (int rep = 0; rep < 2; rep++) {
                    int i = t + rep * 256;
                    int p = i ^ j;
                    if (p > i) {
                        bool up = ((i & k) == 0);
                        int ki = keys[i], kp = keys[p];
                        if ((ki > kp) == up) {
                            keys[i] = kp; keys[p] = ki;
                            int vi = vals[i]; vals[i] = vals[p]; vals[p] = vi;
                        }
                    }
                }
                __syncthreads();
            }
        }
#pragma unroll
        for (int rep = 0; rep < 2; rep++) {
            int i = t + rep * 256;
            g_sidx[b][i]  = keys[i];
            g_sperm[b][i] = vals[i];
        }
    } else {
        long base = (long)(blockIdx.x - BSZ) * 256 + threadIdx.x;
        long stride = (long)(gridDim.x - BSZ) * 256;
        float4 z = make_float4(0.f, 0.f, 0.f, 0.f);
        for (long j = base; j < na4; j += stride) a[j] = z;
        for (long j = base; j < nb4; j += stride) b4[j] = z;
    }
}

// ---------------------------------------------------------------------------
// tf32 tensor-core GEMM core: 64x64 tile, 256 threads (4x2 warps of 16x32),
// BK=32, 3-stage cp.async pipeline, mma.sync.m16n8k8.tf32.
// TB=true:  C[m,n] (+)= alpha * sum_k A[m,k] * B[n,k]   (NT, both K-major)
// TB=false: C[m,n] (+)= alpha * sum_k A[m,k] * B[k,n]   (NN)
// ATOMIC=true: accumulate into C with atomicAdd (for K-split partial sums).
// ---------------------------------------------------------------------------
__device__ __forceinline__ void cp16(void* dst, const void* src)
{
    uint32_t d = (uint32_t)__cvta_generic_to_shared(dst);
    asm volatile("cp.async.cg.shared.global [%0], [%1], 16;\n"
                 :: "r"(d), "l"(src));
}
__device__ __forceinline__ void cp_commit()
{
    asm volatile("cp.async.commit_group;\n" ::: "memory");
}
__device__ __forceinline__ void cp_wait0()
{
    asm volatile("cp.async.wait_group 0;\n" ::: "memory");
}
__device__ __forceinline__ void cp_wait1()
{
    asm volatile("cp.async.wait_group 1;\n" ::: "memory");
}
__device__ __forceinline__ void mma_tf32(float* d, const uint32_t* a,
                                         const uint32_t* b)
{
    asm volatile(
        "mma.sync.aligned.m16n8k8.row.col.f32.tf32.tf32.f32 "
        "{%0,%1,%2,%3}, {%4,%5,%6,%7}, {%8,%9}, {%0,%1,%2,%3};\n"
        : "+f"(d[0]), "+f"(d[1]), "+f"(d[2]), "+f"(d[3])
        : "r"(a[0]), "r"(a[1]), "r"(a[2]), "r"(a[3]),
          "r"(b[0]), "r"(b[1]));
}

#define PA 36   // smem pitch, K-major tiles (banks 4*gid+tig: conflict-free)
#define PB 72   // smem pitch, NN B tile     (banks 8*tig+gid: conflict-free)

template <bool TB, bool ATOMIC>
__device__ __forceinline__ void gemm_core(
    const float* __restrict__ A, const float* __restrict__ B,
    float* __restrict__ C, int lda, int ldb, int ldc,
    int m0, int n0, int kOff, int kLen, float alpha, float* smem)
{
    float (*As)[TILEF] = reinterpret_cast<float(*)[TILEF]>(smem);
    float (*Bs)[TILEF] = reinterpret_cast<float(*)[TILEF]>(smem
                                                           + STAGES * TILEF);

    const int tid  = threadIdx.x;
    const int lane = tid & 31, w = tid >> 5;
    const int gid = lane >> 2, tig = lane & 3;
    const int wm = (w & 3) * 16, wn = (w >> 2) * 32;

    const int NK = kLen / 32;

    auto loadA = [&](int st, int kt) {
        int k0 = kOff + kt * 32;
#pragma unroll
        for (int i = 0; i < 2; i++) {
            int id = tid + i * 256;
            int row = id >> 3, cc = id & 7;
            cp16(&As[st][row * PA + cc * 4],
                 A + (long)(m0 + row) * lda + k0 + cc * 4);
        }
    };
    auto loadB = [&](int st, int kt) {
        int k0 = kOff + kt * 32;
        if (TB) {
#pragma unroll
            for (int i = 0; i < 2; i++) {
                int id = tid + i * 256;
                int row = id >> 3, cc = id & 7;
                cp16(&Bs[st][row * PA + cc * 4],
                     B + (long)(n0 + row) * ldb + k0 + cc * 4);
            }
        } else {
#pragma unroll
            for (int i = 0; i < 2; i++) {
                int id = tid + i * 256;
                int row = id >> 4, cc = id & 15;
                cp16(&Bs[st][row * PB + cc * 4],
                     B + (long)(k0 + row) * ldb + n0 + cc * 4);
            }
        }
    };

    float acc[4][4] = {};

    // prologue: 2 stages in flight
    loadA(0, 0); loadB(0, 0); cp_commit();
    if (NK > 1) { loadA(1, 1); loadB(1, 1); cp_commit(); }

    int buf = 0;        // stage being consumed this iter
    int ls  = 2;        // stage the next prefetch writes into
    for (int kt = 0; kt < NK; kt++) {
        if (kt < NK - 1) cp_wait1(); else cp_wait0();
        __syncthreads();
        if (kt + 2 < NK) {
            loadA(ls, kt + 2);
            loadB(ls, kt + 2);
            cp_commit();
            ls = (ls == STAGES - 1) ? 0 : ls + 1;
        }
#pragma unroll
        for (int ks = 0; ks < 4; ks++) {
            const int kk = ks * 8;
            uint32_t a[4];
            {
                int rb = wm + gid;
                a[0] = __float_as_uint(As[buf][(rb)     * PA + kk + tig]);
                a[1] = __float_as_uint(As[buf][(rb + 8) * PA + kk + tig]);
                a[2] = __float_as_uint(As[buf][(rb)     * PA + kk + tig + 4]);
                a[3] = __float_as_uint(As[buf][(rb + 8) * PA + kk + tig + 4]);
            }
            uint32_t b[4][2];
#pragma unroll
            for (int nj = 0; nj < 4; nj++) {
                int cb = wn + nj * 8 + gid;
                if (TB) {
                    b[nj][0] = __float_as_uint(Bs[buf][cb * PA + kk + tig]);
                    b[nj][1] = __float_as_uint(Bs[buf][cb * PA + kk + tig + 4]);
                } else {
                    b[nj][0] = __float_as_uint(Bs[buf][(kk + tig)     * PB + cb]);
                    b[nj][1] = __float_as_uint(Bs[buf][(kk + tig + 4) * PB + cb]);
                }
            }
#pragma unroll
            for (int nj = 0; nj < 4; nj++)
                mma_tf32(acc[nj], a, b[nj]);
        }
        buf = (buf == STAGES - 1) ? 0 : buf + 1;
    }

#pragma unroll
    for (int nj = 0; nj < 4; nj++) {
        int r0 = m0 + wm + gid;
        int c0 = n0 + wn + nj * 8 + 2 * tig;
        if (ATOMIC) {
            atomicAdd(&C[(long)r0 * ldc + c0],           acc[nj][0] * alpha);
            atomicAdd(&C[(long)r0 * ldc + c0 + 1],       acc[nj][1] * alpha);
            atomicAdd(&C[(long)(r0 + 8) * ldc + c0],     acc[nj][2] * alpha);
            atomicAdd(&C[(long)(r0 + 8) * ldc + c0 + 1], acc[nj][3] * alpha);
        } else {
            C[(long)r0 * ldc + c0]           = acc[nj][0] * alpha;
            C[(long)r0 * ldc + c0 + 1]       = acc[nj][1] * alpha;
            C[(long)(r0 + 8) * ldc + c0]     = acc[nj][2] * alpha;
            C[(long)(r0 + 8) * ldc + c0 + 1] = acc[nj][3] * alpha;
        }
    }
}

// ---------------------------------------------------------------------------
// G = Wm @ We^T * scale  (512x512, NT), K-split x4 with atomic accumulation.
// ---------------------------------------------------------------------------
__global__ __launch_bounds__(256) void k_G(
    const float* __restrict__ Wm, const float* __restrict__ We,
    float* __restrict__ G, float scale)
{
    extern __shared__ float smem[];
    gemm_core<true, true>(Wm, We, G, HD, HD, HD,
                          blockIdx.y * 64, blockIdx.x * 64,
                          blockIdx.z * 128, 128, scale, smem);
}

// ---------------------------------------------------------------------------
// T = M_flat @ G  (1024x512, NN), K-split x2 with atomic accumulation.
// ---------------------------------------------------------------------------
__global__ __launch_bounds__(256) void k_T(
    const float* __restrict__ M, const float* __restrict__ G,
    float* __restrict__ T)
{
    extern __shared__ float smem[];
    gemm_core<false, true>(M, G, T, HD, HD, HD,
                           blockIdx.y * 64, blockIdx.x * 64,
                           blockIdx.z * 256, 256, 1.f, smem);
}

// ---------------------------------------------------------------------------
// logits[b] = T[b] @ E[b]^T (NT), K-split x4 into 4 separate partial buffers.
// grid = (8, 4, 16): z = b*4 + h.
// ---------------------------------------------------------------------------
__global__ __launch_bounds__(256) void k_log(
    const float* __restrict__ T, const float* __restrict__ E,
    float* __restrict__ logs)
{
    extern __shared__ float smem[];
    int z = blockIdx.z;
    int b = z >> 2, h = z & 3;
    const float* A = T + (long)b * LM * HD;
    const float* B = E + (long)b * LE * HD;
    float* C = logs + (long)h * BSZ * LM * LE + (long)b * LM * LE;
    gemm_core<true, false>(A, B, C, HD, HD, LE,
                           blockIdx.y * 64, blockIdx.x * 64,
                           h * 128, 128, 1.f, smem);
}

// ---------------------------------------------------------------------------
// Block reduction for 512 threads (16 warps). red16 is a 16-float smem array.
// ---------------------------------------------------------------------------
__device__ __forceinline__ float bred512(float v, bool mx, float* red16,
                                         int lane, int w)
{
#pragma unroll
    for (int o = 16; o > 0; o >>= 1) {
        float u = __shfl_xor_sync(0xffffffffu, v, o);
        v = mx ? fmaxf(v, u) : v + u;
    }
    if (lane == 0) red16[w] = v;
    __syncthreads();
    float x = red16[lane & 15];
#pragma unroll
    for (int o = 8; o > 0; o >>= 1) {
        float u = __shfl_xor_sync(0xffffffffu, x, o);
        x = mx ? fmaxf(x, u) : x + u;
    }
    __syncthreads();   // red16 free for next use
    return x;          // identical in every thread
}

// ---------------------------------------------------------------------------
// Fused output kernel, one block per row (1024 blocks, 512 threads, ~7 KB
// smem). Uses the per-batch SORTED index list:
//   lambda + dual softmax; permute weights into sorted order;
//   threads 0..250 build spanPtr[] (sorted-list range per 128-float span);
//   each WARP then owns spans: lane L composes float4 at span*128 + L*4 in
//   registers (zeros + the span's few entries via broadcast LDS) and issues
//   __stcs. Warp writes 512 contiguous bytes -> fully coalesced streaming
//   stores, no smem row buffer, no readback, no global atomics.
// ---------------------------------------------------------------------------
__global__ __launch_bounds__(512) void k_scatter(
    const float* __restrict__ bq, const float* __restrict__ bc,
    const float* __restrict__ D, const float* __restrict__ Cq,
    const float* __restrict__ Cc, const float* __restrict__ Wl,
    const float* __restrict__ bl, const float* __restrict__ logs,
    float* __restrict__ out)
{
    __shared__ float wgt[LE];       // weight by original position e
    __shared__ float ws[LE];        // weight by sorted slot
    __shared__ int   sidx[LE];      // sorted vocab indices
    __shared__ int   spanPtr[NSPAN + 1];
    __shared__ float red16[16];

    const int r = blockIdx.x;                // 0 .. BSZ*LM-1
    const int b = r >> 8;                    // r / LM
    const int t = threadIdx.x, lane = t & 31, w = t >> 5;

    // lambda (512 threads x 1 element each of the 3 concatenated chunks)
    const float* dr  = D  + (long)r * HD;
    const float* cqr = Cq + (long)r * HD;
    const float* ccr = Cc + (long)r * HD;
    float s = dr[t] * Wl[t] + cqr[t] * Wl[HD + t] + ccr[t] * Wl[2 * HD + t];
    s = bred512(s, false, red16, lane, w);
    float lam = 1.f / (1.f + __expf(-(s + bl[0])));

    // logits: one element per thread (LE == 512), sum of 4 K-split partials
    const long rl = (long)r * LE + t;
    const long str = (long)BSZ * LM * LE;
    float l = logs[rl] + logs[str + rl] + logs[2 * str + rl] + logs[3 * str + rl];
    float vq = l + bq[b * LE + t];
    float vc = l + bc[b * LE + t];

    float mq = bred512(vq, true, red16, lane, w);
    float mc = bred512(vc, true, red16, lane, w);
    float eq = __expf(vq - mq);
    float ec = __expf(vc - mc);
    float sq = bred512(eq, false, red16, lane, w);
    float sc = bred512(ec, false, red16, lane, w);

    wgt[t] = lam * eq / sq + (1.f - lam) * ec / sc;
    sidx[t] = g_sidx[b][t];
    int sp = g_sperm[b][t];
    __syncthreads();
    ws[t] = wgt[sp];

    // span pointers: lower_bound(sidx, span*128) for span = 0..NSPAN
    if (t <= NSPAN) {
        int target = t * 128;
        int lo = 0, hi = LE;
        while (lo < hi) {
            int mid = (lo + hi) >> 1;
            if (sidx[mid] < target) lo = mid + 1; else hi = mid;
        }
        spanPtr[t] = lo;
    }
    __syncthreads();

    // warp-per-span output: lane composes its float4, warp stores 512B runs
    float4* o4 = (float4*)(out + (long)r * VOC);
#pragma unroll
    for (int it = 0; it < 16; it++) {
        int sidx_span = it * 16 + w;
        if (sidx_span >= NSPAN) break;
        int lo = spanPtr[sidx_span], hi = spanPtr[sidx_span + 1];
        int base = sidx_span * 128 + lane * 4;
        float4 f = make_float4(0.f, 0.f, 0.f, 0.f);
        for (int e = lo; e < hi; e++) {
            int d = sidx[e] - base;       // broadcast LDS across the warp
            float v = ws[e];
            if (d == 0) f.x += v;
            else if (d == 1) f.y += v;
            else if (d == 2) f.z += v;
            else if (d == 3) f.w += v;
        }
        __stcs(o4 + (base >> 2), f);
    }
}

// ---------------------------------------------------------------------------
extern "C" void kernel_launch(void* const* d_in, const int* in_sizes, int n_in,
                              void* d_out, int out_size)
{
    const int*   inputs = (const int*)  d_in[0];
    const float* D      = (const float*)d_in[1];
    const float* Cq     = (const float*)d_in[2];
    const float* Cc     = (const float*)d_in[3];
    const float* Mi     = (const float*)d_in[4];
    const float* E      = (const float*)d_in[5];
    const float* bq     = (const float*)d_in[6];
    const float* bc     = (const float*)d_in[7];
    const float* Wl     = (const float*)d_in[8];
    const float* bl     = (const float*)d_in[9];
    const float* We     = (const float*)d_in[10];
    const float* Wm     = (const float*)d_in[11];
    float* out = (float*)d_out;

    float *gG, *gT, *gL;
    cudaGetSymbolAddress((void**)&gG, g_G);
    cudaGetSymbolAddress((void**)&gT, g_T);
    cudaGetSymbolAddress((void**)&gL, g_log);

    static bool init = false;
    if (!init) {
        cudaFuncSetAttribute(k_G,
                             cudaFuncAttributeMaxDynamicSharedMemorySize,
                             GSMEM);
        cudaFuncSetAttribute(k_T,
                             cudaFuncAttributeMaxDynamicSharedMemorySize,
                             GSMEM);
        cudaFuncSetAttribute(k_log,
                             cudaFuncAttributeMaxDynamicSharedMemorySize,
                             GSMEM);
        init = true;
    }

    const float scale = 0.044194173824159216f;  // 512^-0.5

    // init: sort per-batch scatter indices (4 blocks) + zero G/T accumulators
    k_init<<<196, 256>>>(inputs, (float4*)gG, HD * HD / 4,
                         (float4*)gT, (long)BSZ * LM * HD / 4);
    // G = Wm @ We^T * scale   (K-split x4, atomic epilogue, 256 blocks)
    k_G<<<dim3(8, 8, 4), 256, GSMEM>>>(Wm, We, gG, scale);
    // T = M_flat @ G          (K-split x2, atomic epilogue, 256 blocks)
    k_T<<<dim3(8, 16, 2), 256, GSMEM>>>(Mi, gG, gT);
    // logits partials         (K-split x4 into 4 buffers, 512 blocks)
    k_log<<<dim3(8, 4, 16), 256, GSMEM>>>(gT, E, gL);
    // fused lambda + softmax + span-coalesced scatter + streamed write
    k_scatter<<<BSZ * LM, 512>>>(bq, bc, D, Cq, Cc, Wl, bl, gL, out);
}

// round 14
// speedup vs baseline: 2.1842x; 1.2359x over previous
#include <cuda_runtime.h>
#include <cstdint>

#define BSZ 4
#define LM  256
#define LE  512
#define HD  512
#define VOC 32000
#define QTR (VOC / 4)    // 8000 floats = 32 KB smem per scatter block

#define STAGES 3
#define TILEF  2304      // floats per A or B stage buffer (64*36 or 32*72)
#define GSMEM  (STAGES * 2 * TILEF * 4)   // 55296 B dynamic smem per GEMM block

// Scratch (device globals; no allocation allowed in kernel_launch)
__device__ float g_G[HD * HD];               // Wm @ We^T * scale    (1 MB)
__device__ float g_T[BSZ * LM * HD];         // M @ G                (2 MB)
__device__ float g_log[BSZ * LM * LE];       // logits               (2 MB)

// ---------------------------------------------------------------------------
// tf32 tensor-core GEMM core: 64x64 tile, 256 threads (4x2 warps of 16x32),
// BK=32, 3-stage cp.async pipeline, mma.sync.m16n8k8.tf32.
// TB=true:  C[m,n] = alpha * sum_k A[m,k] * B[n,k]   (NT, both K-major)
// TB=false: C[m,n] = alpha * sum_k A[m,k] * B[k,n]   (NN)
// ---------------------------------------------------------------------------
__device__ __forceinline__ void cp16(void* dst, const void* src)
{
    uint32_t d = (uint32_t)__cvta_generic_to_shared(dst);
    asm volatile("cp.async.cg.shared.global [%0], [%1], 16;\n"
                 :: "r"(d), "l"(src));
}
__device__ __forceinline__ void cp_commit()
{
    asm volatile("cp.async.commit_group;\n" ::: "memory");
}
__device__ __forceinline__ void cp_wait0()
{
    asm volatile("cp.async.wait_group 0;\n" ::: "memory");
}
__device__ __forceinline__ void cp_wait1()
{
    asm volatile("cp.async.wait_group 1;\n" ::: "memory");
}
__device__ __forceinline__ void mma_tf32(float* d, const uint32_t* a,
                                         const uint32_t* b)
{
    asm volatile(
        "mma.sync.aligned.m16n8k8.row.col.f32.tf32.tf32.f32 "
        "{%0,%1,%2,%3}, {%4,%5,%6,%7}, {%8,%9}, {%0,%1,%2,%3};\n"
        : "+f"(d[0]), "+f"(d[1]), "+f"(d[2]), "+f"(d[3])
        : "r"(a[0]), "r"(a[1]), "r"(a[2]), "r"(a[3]),
          "r"(b[0]), "r"(b[1]));
}

#define PA 36   // smem pitch, K-major tiles (banks 4*gid+tig: conflict-free)
#define PB 72   // smem pitch, NN B tile     (banks 8*tig+gid: conflict-free)

template <bool TB>
__device__ __forceinline__ void gemm_core(
    const float* __restrict__ A, const float* __restrict__ B,
    float* __restrict__ C, int lda, int ldb, int ldc,
    int m0, int n0, int kLen, float alpha, float* smem)
{
    float (*As)[TILEF] = reinterpret_cast<float(*)[TILEF]>(smem);
    float (*Bs)[TILEF] = reinterpret_cast<float(*)[TILEF]>(smem
                                                           + STAGES * TILEF);

    const int tid  = threadIdx.x;
    const int lane = tid & 31, w = tid >> 5;
    const int gid = lane >> 2, tig = lane & 3;
    const int wm = (w & 3) * 16, wn = (w >> 2) * 32;

    const int NK = kLen / 32;

    auto loadA = [&](int st, int kt) {
        int k0 = kt * 32;
#pragma unroll
        for (int i = 0; i < 2; i++) {
            int id = tid + i * 256;
            int row = id >> 3, cc = id & 7;
            cp16(&As[st][row * PA + cc * 4],
                 A + (long)(m0 + row) * lda + k0 + cc * 4);
        }
    };
    auto loadB = [&](int st, int kt) {
        int k0 = kt * 32;
        if (TB) {
#pragma unroll
            for (int i = 0; i < 2; i++) {
                int id = tid + i * 256;
                int row = id >> 3, cc = id & 7;
                cp16(&Bs[st][row * PA + cc * 4],
                     B + (long)(n0 + row) * ldb + k0 + cc * 4);
            }
        } else {
#pragma unroll
            for (int i = 0; i < 2; i++) {
                int id = tid + i * 256;
                int row = id >> 4, cc = id & 15;
                cp16(&Bs[st][row * PB + cc * 4],
                     B + (long)(k0 + row) * ldb + n0 + cc * 4);
            }
        }
    };

    float acc[4][4] = {};

    // prologue: 2 stages in flight
    loadA(0, 0); loadB(0, 0); cp_commit();
    if (NK > 1) { loadA(1, 1); loadB(1, 1); cp_commit(); }

    int buf = 0;        // stage being consumed this iter
    int ls  = 2;        // stage the next prefetch writes into
    for (int kt = 0; kt < NK; kt++) {
        if (kt < NK - 1) cp_wait1(); else cp_wait0();
        __syncthreads();
        if (kt + 2 < NK) {
            loadA(ls, kt + 2);
            loadB(ls, kt + 2);
            cp_commit();
            ls = (ls == STAGES - 1) ? 0 : ls + 1;
        }
#pragma unroll
        for (int ks = 0; ks < 4; ks++) {
            const int kk = ks * 8;
            uint32_t a[4];
            {
                int rb = wm + gid;
                a[0] = __float_as_uint(As[buf][(rb)     * PA + kk + tig]);
                a[1] = __float_as_uint(As[buf][(rb + 8) * PA + kk + tig]);
                a[2] = __float_as_uint(As[buf][(rb)     * PA + kk + tig + 4]);
                a[3] = __float_as_uint(As[buf][(rb + 8) * PA + kk + tig + 4]);
            }
            uint32_t b[4][2];
#pragma unroll
            for (int nj = 0; nj < 4; nj++) {
                int cb = wn + nj * 8 + gid;
                if (TB) {
                    b[nj][0] = __float_as_uint(Bs[buf][cb * PA + kk + tig]);
                    b[nj][1] = __float_as_uint(Bs[buf][cb * PA + kk + tig + 4]);
                } else {
                    b[nj][0] = __float_as_uint(Bs[buf][(kk + tig)     * PB + cb]);
                    b[nj][1] = __float_as_uint(Bs[buf][(kk + tig + 4) * PB + cb]);
                }
            }
#pragma unroll
            for (int nj = 0; nj < 4; nj++)
                mma_tf32(acc[nj], a, b[nj]);
        }
        buf = (buf == STAGES - 1) ? 0 : buf + 1;
    }

#pragma unroll
    for (int nj = 0; nj < 4; nj++) {
        int r0 = m0 + wm + gid;
        int c0 = n0 + wn + nj * 8 + 2 * tig;
        C[(long)r0 * ldc + c0]           = acc[nj][0] * alpha;
        C[(long)r0 * ldc + c0 + 1]       = acc[nj][1] * alpha;
        C[(long)(r0 + 8) * ldc + c0]     = acc[nj][2] * alpha;
        C[(long)(r0 + 8) * ldc + c0 + 1] = acc[nj][3] * alpha;
    }
}

// ---------------------------------------------------------------------------
// G = Wm @ We^T * scale  (512x512, NT), full K, plain store. grid (8, 8).
// ---------------------------------------------------------------------------
__global__ __launch_bounds__(256) void k_G(
    const float* __restrict__ Wm, const float* __restrict__ We,
    float* __restrict__ G, float scale)
{
    extern __shared__ float smem[];
    gemm_core<true>(Wm, We, G, HD, HD, HD,
                    blockIdx.y * 64, blockIdx.x * 64, HD, scale, smem);
}

// ---------------------------------------------------------------------------
// T = M_flat @ G  (1024x512, NN), full K, plain store. grid (8, 16).
// ---------------------------------------------------------------------------
__global__ __launch_bounds__(256) void k_T(
    const float* __restrict__ M, const float* __restrict__ G,
    float* __restrict__ T)
{
    extern __shared__ float smem[];
    gemm_core<false>(M, G, T, HD, HD, HD,
                     blockIdx.y * 64, blockIdx.x * 64, HD, 1.f, smem);
}

// ---------------------------------------------------------------------------
// logits[b] = T[b] @ E[b]^T (NT), full K, single buffer. grid (8, 4, BSZ).
// ---------------------------------------------------------------------------
__global__ __launch_bounds__(256) void k_log(
    const float* __restrict__ T, const float* __restrict__ E,
    float* __restrict__ logs)
{
    extern __shared__ float smem[];
    int b = blockIdx.z;
    const float* A = T + (long)b * LM * HD;
    const float* B = E + (long)b * LE * HD;
    float* C = logs + (long)b * LM * LE;
    gemm_core<true>(A, B, C, HD, HD, LE,
                    blockIdx.y * 64, blockIdx.x * 64, HD, 1.f, smem);
}

// ---------------------------------------------------------------------------
// Block reduction for 256 threads (8 warps). red8 is an 8-float smem array.
// ---------------------------------------------------------------------------
__device__ __forceinline__ float bred256(float v, bool mx, float* red8,
                                         int lane, int w)
{
#pragma unroll
    for (int o = 16; o > 0; o >>= 1) {
        float u = __shfl_xor_sync(0xffffffffu, v, o);
        v = mx ? fmaxf(v, u) : v + u;
    }
    if (lane == 0) red8[w] = v;
    __syncthreads();
    float x = red8[lane & 7];
#pragma unroll
    for (int o = 4; o > 0; o >>= 1) {
        float u = __shfl_xor_sync(0xffffffffu, x, o);
        x = mx ? fmaxf(x, u) : x + u;
    }
    __syncthreads();   // red8 free for next use
    return x;          // identical in every thread
}

// ---------------------------------------------------------------------------
// Fused output kernel. grid = (4 vocab quarters, 1024 rows), 256 threads,
// 32 KB static smem (quarter of an output row) -> 7 blocks/SM. Per block:
//   zero smem quarter-row; compute lambda inline; dual softmax over the
//   logits row; scatter-add into smem (atomicAdd, tiny); stream the
//   quarter-row to GMEM with __stcs. Proven R7 pattern, finer tiling.
// ---------------------------------------------------------------------------
__global__ __launch_bounds__(256) void k_scatter(
    const int* __restrict__ idx, const float* __restrict__ bq,
    const float* __restrict__ bc, const float* __restrict__ D,
    const float* __restrict__ Cq, const float* __restrict__ Cc,
    const float* __restrict__ Wl, const float* __restrict__ bl,
    const float* __restrict__ logs, float* __restrict__ out)
{
    __shared__ float vrow[QTR];              // 32 KB
    __shared__ float red8[8];

    const int r = blockIdx.y;                // 0 .. BSZ*LM-1
    const int q = blockIdx.x;                // vocab quarter
    const int b = r >> 8;                    // r / LM
    const int t = threadIdx.x, lane = t & 31, w = t >> 5;

    // zero the smem quarter-row (2000 float4)
    float4* v4 = (float4*)vrow;
    for (int i = t; i < QTR / 4; i += 256)
        v4[i] = make_float4(0.f, 0.f, 0.f, 0.f);

    // lambda (256 threads x 2 elements of each of the 3 chunks)
    const float* dr  = D  + (long)r * HD;
    const float* cqr = Cq + (long)r * HD;
    const float* ccr = Cc + (long)r * HD;
    float s = 0.f;
#pragma unroll
    for (int i = 0; i < 2; i++) {
        int j = t + i * 256;
        s += dr[j] * Wl[j] + cqr[j] * Wl[HD + j] + ccr[j] * Wl[2 * HD + j];
    }
    s = bred256(s, false, red8, lane, w);
    float lam = 1.f / (1.f + __expf(-(s + bl[0])));

    // logits: 2 elements per thread (LE == 512)
    float vq[2], vc[2];
#pragma unroll
    for (int i = 0; i < 2; i++) {
        int e = t + i * 256;
        float l = logs[(long)r * LE + e];
        vq[i] = l + bq[b * LE + e];
        vc[i] = l + bc[b * LE + e];
    }

    float mq = bred256(fmaxf(vq[0], vq[1]), true, red8, lane, w);
    float mc = bred256(fmaxf(vc[0], vc[1]), true, red8, lane, w);
    float eq[2], ec[2];
    eq[0] = __expf(vq[0] - mq); eq[1] = __expf(vq[1] - mq);
    ec[0] = __expf(vc[0] - mc); ec[1] = __expf(vc[1] - mc);
    float sq = bred256(eq[0] + eq[1], false, red8, lane, w);
    float sc = bred256(ec[0] + ec[1], false, red8, lane, w);

    float iq = lam / sq, ic = (1.f - lam) / sc;
#pragma unroll
    for (int i = 0; i < 2; i++) {
        int e = t + i * 256;
        int ix = idx[b * LE + e] - q * QTR;
        if (ix >= 0 && ix < QTR)
            atomicAdd(&vrow[ix], eq[i] * iq + ec[i] * ic);
    }
    __syncthreads();

    // stream the quarter-row out (write-once; no pre-zero needed)
    float4* orow4 = (float4*)(out + (long)r * VOC + (long)q * QTR);
    for (int i = t; i < QTR / 4; i += 256)
        __stcs(orow4 + i, v4[i]);
}

// ---------------------------------------------------------------------------
extern "C" void kernel_launch(void* const* d_in, const int* in_sizes, int n_in,
                              void* d_out, int out_size)
{
    const int*   inputs = (const int*)  d_in[0];
    const float* D      = (const float*)d_in[1];
    const float* Cq     = (const float*)d_in[2];
    const float* Cc     = (const float*)d_in[3];
    const float* Mi     = (const float*)d_in[4];
    const float* E      = (const float*)d_in[5];
    const float* bq     = (const float*)d_in[6];
    const float* bc     = (const float*)d_in[7];
    const float* Wl     = (const float*)d_in[8];
    const float* bl     = (const float*)d_in[9];
    const float* We     = (const float*)d_in[10];
    const float* Wm     = (const float*)d_in[11];
    float* out = (float*)d_out;

    float *gG, *gT, *gL;
    cudaGetSymbolAddress((void**)&gG, g_G);
    cudaGetSymbolAddress((void**)&gT, g_T);
    cudaGetSymbolAddress((void**)&gL, g_log);

    static bool init = false;
    if (!init) {
        cudaFuncSetAttribute(k_G,
                             cudaFuncAttributeMaxDynamicSharedMemorySize,
                             GSMEM);
        cudaFuncSetAttribute(k_T,
                             cudaFuncAttributeMaxDynamicSharedMemorySize,
                             GSMEM);
        cudaFuncSetAttribute(k_log,
                             cudaFuncAttributeMaxDynamicSharedMemorySize,
                             GSMEM);
        init = true;
    }

    const float scale = 0.044194173824159216f;  // 512^-0.5

    // G = Wm @ We^T * scale   (full K, 64 blocks)
    k_G<<<dim3(8, 8), 256, GSMEM>>>(Wm, We, gG, scale);
    // T = M_flat @ G          (full K, 128 blocks)
    k_T<<<dim3(8, 16), 256, GSMEM>>>(Mi, gG, gT);
    // logits                  (full K, 128 blocks, single buffer)
    k_log<<<dim3(8, 4, BSZ), 256, GSMEM>>>(gT, E, gL);
    // fused lambda + softmax + scatter + streamed quarter-row write
    k_scatter<<<dim3(4, BSZ * LM), 256>>>(
        inputs, bq, bc, D, Cq, Cc, Wl, bl, gL, out);
}

// round 15
// speedup vs baseline: 2.2548x; 1.0323x over previous
#include <cuda_runtime.h>
#include <cstdint>

#define BSZ 4
#define LM  256
#define LE  512
#define HD  512
#define VOC 32000
#define QTR (VOC / 4)    // 8000 floats = 32 KB smem values per scatter block
#define NBM (QTR / 32)   // 250 bitmap words

#define STAGES 3
#define TILEF  2304      // floats per A or B stage buffer (64*36 or 32*72)
#define GSMEM  (STAGES * 2 * TILEF * 4)   // 55296 B dynamic smem per GEMM block

// Scratch (device globals; no allocation allowed in kernel_launch)
__device__ float g_G[HD * HD];               // Wm @ We^T * scale    (1 MB)
__device__ float g_T[BSZ * LM * HD];         // M @ G                (2 MB)
__device__ float g_log[BSZ * LM * LE];       // logits               (2 MB)

// ---------------------------------------------------------------------------
// tf32 tensor-core GEMM core: 64x64 tile, 256 threads (4x2 warps of 16x32),
// BK=32, 3-stage cp.async pipeline, mma.sync.m16n8k8.tf32.
// TB=true:  C[m,n] = alpha * sum_k A[m,k] * B[n,k]   (NT, both K-major)
// TB=false: C[m,n] = alpha * sum_k A[m,k] * B[k,n]   (NN)
// ---------------------------------------------------------------------------
__device__ __forceinline__ void cp16(void* dst, const void* src)
{
    uint32_t d = (uint32_t)__cvta_generic_to_shared(dst);
    asm volatile("cp.async.cg.shared.global [%0], [%1], 16;\n"
                 :: "r"(d), "l"(src));
}
__device__ __forceinline__ void cp_commit()
{
    asm volatile("cp.async.commit_group;\n" ::: "memory");
}
__device__ __forceinline__ void cp_wait0()
{
    asm volatile("cp.async.wait_group 0;\n" ::: "memory");
}
__device__ __forceinline__ void cp_wait1()
{
    asm volatile("cp.async.wait_group 1;\n" ::: "memory");
}
__device__ __forceinline__ void mma_tf32(float* d, const uint32_t* a,
                                         const uint32_t* b)
{
    asm volatile(
        "mma.sync.aligned.m16n8k8.row.col.f32.tf32.tf32.f32 "
        "{%0,%1,%2,%3}, {%4,%5,%6,%7}, {%8,%9}, {%0,%1,%2,%3};\n"
        : "+f"(d[0]), "+f"(d[1]), "+f"(d[2]), "+f"(d[3])
        : "r"(a[0]), "r"(a[1]), "r"(a[2]), "r"(a[3]),
          "r"(b[0]), "r"(b[1]));
}

#define PA 36   // smem pitch, K-major tiles (banks 4*gid+tig: conflict-free)
#define PB 72   // smem pitch, NN B tile     (banks 8*tig+gid: conflict-free)

template <bool TB>
__device__ __forceinline__ void gemm_core(
    const float* __restrict__ A, const float* __restrict__ B,
    float* __restrict__ C, int lda, int ldb, int ldc,
    int m0, int n0, int kLen, float alpha, float* smem)
{
    float (*As)[TILEF] = reinterpret_cast<float(*)[TILEF]>(smem);
    float (*Bs)[TILEF] = reinterpret_cast<float(*)[TILEF]>(smem
                                                           + STAGES * TILEF);

    const int tid  = threadIdx.x;
    const int lane = tid & 31, w = tid >> 5;
    const int gid = lane >> 2, tig = lane & 3;
    const int wm = (w & 3) * 16, wn = (w >> 2) * 32;

    const int NK = kLen / 32;

    auto loadA = [&](int st, int kt) {
        int k0 = kt * 32;
#pragma unroll
        for (int i = 0; i < 2; i++) {
            int id = tid + i * 256;
            int row = id >> 3, cc = id & 7;
            cp16(&As[st][row * PA + cc * 4],
                 A + (long)(m0 + row) * lda + k0 + cc * 4);
        }
    };
    auto loadB = [&](int st, int kt) {
        int k0 = kt * 32;
        if (TB) {
#pragma unroll
            for (int i = 0; i < 2; i++) {
                int id = tid + i * 256;
                int row = id >> 3, cc = id & 7;
                cp16(&Bs[st][row * PA + cc * 4],
                     B + (long)(n0 + row) * ldb + k0 + cc * 4);
            }
        } else {
#pragma unroll
            for (int i = 0; i < 2; i++) {
                int id = tid + i * 256;
                int row = id >> 4, cc = id & 15;
                cp16(&Bs[st][row * PB + cc * 4],
                     B + (long)(k0 + row) * ldb + n0 + cc * 4);
            }
        }
    };

    float acc[4][4] = {};

    // prologue: 2 stages in flight
    loadA(0, 0); loadB(0, 0); cp_commit();
    if (NK > 1) { loadA(1, 1); loadB(1, 1); cp_commit(); }

    int buf = 0;        // stage being consumed this iter
    int ls  = 2;        // stage the next prefetch writes into
    for (int kt = 0; kt < NK; kt++) {
        if (kt < NK - 1) cp_wait1(); else cp_wait0();
        __syncthreads();
        if (kt + 2 < NK) {
            loadA(ls, kt + 2);
            loadB(ls, kt + 2);
            cp_commit();
            ls = (ls == STAGES - 1) ? 0 : ls + 1;
        }
#pragma unroll
        for (int ks = 0; ks < 4; ks++) {
            const int kk = ks * 8;
            uint32_t a[4];
            {
                int rb = wm + gid;
                a[0] = __float_as_uint(As[buf][(rb)     * PA + kk + tig]);
                a[1] = __float_as_uint(As[buf][(rb + 8) * PA + kk + tig]);
                a[2] = __float_as_uint(As[buf][(rb)     * PA + kk + tig + 4]);
                a[3] = __float_as_uint(As[buf][(rb + 8) * PA + kk + tig + 4]);
            }
            uint32_t b[4][2];
#pragma unroll
            for (int nj = 0; nj < 4; nj++) {
                int cb = wn + nj * 8 + gid;
                if (TB) {
                    b[nj][0] = __float_as_uint(Bs[buf][cb * PA + kk + tig]);
                    b[nj][1] = __float_as_uint(Bs[buf][cb * PA + kk + tig + 4]);
                } else {
                    b[nj][0] = __float_as_uint(Bs[buf][(kk + tig)     * PB + cb]);
                    b[nj][1] = __float_as_uint(Bs[buf][(kk + tig + 4) * PB + cb]);
                }
            }
#pragma unroll
            for (int nj = 0; nj < 4; nj++)
                mma_tf32(acc[nj], a, b[nj]);
        }
        buf = (buf == STAGES - 1) ? 0 : buf + 1;
    }

#pragma unroll
    for (int nj = 0; nj < 4; nj++) {
        int r0 = m0 + wm + gid;
        int c0 = n0 + wn + nj * 8 + 2 * tig;
        C[(long)r0 * ldc + c0]           = acc[nj][0] * alpha;
        C[(long)r0 * ldc + c0 + 1]       = acc[nj][1] * alpha;
        C[(long)(r0 + 8) * ldc + c0]     = acc[nj][2] * alpha;
        C[(long)(r0 + 8) * ldc + c0 + 1] = acc[nj][3] * alpha;
    }
}

// ---------------------------------------------------------------------------
// G = Wm @ We^T * scale  (512x512, NT), full K, plain store. grid (8, 8).
// ---------------------------------------------------------------------------
__global__ __launch_bounds__(256) void k_G(
    const float* __restrict__ Wm, const float* __restrict__ We,
    float* __restrict__ G, float scale)
{
    extern __shared__ float smem[];
    gemm_core<true>(Wm, We, G, HD, HD, HD,
                    blockIdx.y * 64, blockIdx.x * 64, HD, scale, smem);
}

// ---------------------------------------------------------------------------
// T = M_flat @ G  (1024x512, NN), full K, plain store. grid (8, 16).
// ---------------------------------------------------------------------------
__global__ __launch_bounds__(256) void k_T(
    const float* __restrict__ M, const float* __restrict__ G,
    float* __restrict__ T)
{
    extern __shared__ float smem[];
    gemm_core<false>(M, G, T, HD, HD, HD,
                     blockIdx.y * 64, blockIdx.x * 64, HD, 1.f, smem);
}

// ---------------------------------------------------------------------------
// logits[b] = T[b] @ E[b]^T (NT), full K, single buffer. grid (8, 4, BSZ).
// ---------------------------------------------------------------------------
__global__ __launch_bounds__(256) void k_log(
    const float* __restrict__ T, const float* __restrict__ E,
    float* __restrict__ logs)
{
    extern __shared__ float smem[];
    int b = blockIdx.z;
    const float* A = T + (long)b * LM * HD;
    const float* B = E + (long)b * LE * HD;
    float* C = logs + (long)b * LM * LE;
    gemm_core<true>(A, B, C, HD, HD, LE,
                    blockIdx.y * 64, blockIdx.x * 64, HD, 1.f, smem);
}

// ---------------------------------------------------------------------------
// Block reduction for 256 threads (8 warps). red8 is an 8-float smem array.
// ---------------------------------------------------------------------------
__device__ __forceinline__ float bred256(float v, bool mx, float* red8,
                                         int lane, int w)
{
#pragma unroll
    for (int o = 16; o > 0; o >>= 1) {
        float u = __shfl_xor_sync(0xffffffffu, v, o);
        v = mx ? fmaxf(v, u) : v + u;
    }
    if (lane == 0) red8[w] = v;
    __syncthreads();
    float x = red8[lane & 7];
#pragma unroll
    for (int o = 4; o > 0; o >>= 1) {
        float u = __shfl_xor_sync(0xffffffffu, x, o);
        x = mx ? fmaxf(x, u) : x + u;
    }
    __syncthreads();   // red8 free for next use
    return x;          // identical in every thread
}

// ---------------------------------------------------------------------------
// Fused output kernel with touched-bitmap. grid = (4 vocab quarters, 1024
// rows), 256 threads, ~33 KB smem. Per block:
//   zero the 250-word bitmap (NOT the 32 KB value tile);
//   lambda + dual softmax (as before);
//   phase A: vrow[ix] = 0 + atomicOr bitmap bit for this block's hits;
//   phase B: atomicAdd(&vrow[ix], w)  (identical arithmetic to R7/R14);
//   readback: per float4, test 4 bitmap bits -> ~97% store register zeros
//   (no LDS), else compose from the few valid vrow slots.
// Cuts L1 traffic from ~3x output bytes to ~1x (STG only).
// ---------------------------------------------------------------------------
__global__ __launch_bounds__(256) void k_scatter(
    const int* __restrict__ idx, const float* __restrict__ bq,
    const float* __restrict__ bc, const float* __restrict__ D,
    const float* __restrict__ Cq, const float* __restrict__ Cc,
    const float* __restrict__ Wl, const float* __restrict__ bl,
    const float* __restrict__ logs, float* __restrict__ out)
{
    __shared__ float vrow[QTR];              // 32 KB (only touched slots valid)
    __shared__ unsigned bm[NBM];             // 1 KB touched bitmap
    __shared__ float red8[8];

    const int r = blockIdx.y;                // 0 .. BSZ*LM-1
    const int q = blockIdx.x;                // vocab quarter
    const int b = r >> 8;                    // r / LM
    const int t = threadIdx.x, lane = t & 31, w = t >> 5;

    // zero the bitmap only (250 words)
    if (t < NBM) bm[t] = 0u;

    // lambda (256 threads x 2 elements of each of the 3 chunks)
    const float* dr  = D  + (long)r * HD;
    const float* cqr = Cq + (long)r * HD;
    const float* ccr = Cc + (long)r * HD;
    float s = 0.f;
#pragma unroll
    for (int i = 0; i < 2; i++) {
        int j = t + i * 256;
        s += dr[j] * Wl[j] + cqr[j] * Wl[HD + j] + ccr[j] * Wl[2 * HD + j];
    }
    s = bred256(s, false, red8, lane, w);   // contains __syncthreads
    float lam = 1.f / (1.f + __expf(-(s + bl[0])));

    // logits: 2 elements per thread (LE == 512)
    float vq[2], vc[2];
#pragma unroll
    for (int i = 0; i < 2; i++) {
        int e = t + i * 256;
        float l = logs[(long)r * LE + e];
        vq[i] = l + bq[b * LE + e];
        vc[i] = l + bc[b * LE + e];
    }

    float mq = bred256(fmaxf(vq[0], vq[1]), true, red8, lane, w);
    float mc = bred256(fmaxf(vc[0], vc[1]), true, red8, lane, w);
    float eq[2], ec[2];
    eq[0] = __expf(vq[0] - mq); eq[1] = __expf(vq[1] - mq);
    ec[0] = __expf(vc[0] - mc); ec[1] = __expf(vc[1] - mc);
    float sq = bred256(eq[0] + eq[1], false, red8, lane, w);
    float sc = bred256(ec[0] + ec[1], false, red8, lane, w);

    float iq = lam / sq, ic = (1.f - lam) / sc;

    // this block's scatter targets within its quarter
    int ix[2]; float wv[2];
#pragma unroll
    for (int i = 0; i < 2; i++) {
        int e = t + i * 256;
        ix[i] = idx[b * LE + e] - q * QTR;
        wv[i] = eq[i] * iq + ec[i] * ic;
    }

    // phase A: zero touched slots + mark bitmap (duplicates all write 0: safe)
#pragma unroll
    for (int i = 0; i < 2; i++)
        if (ix[i] >= 0 && ix[i] < QTR) {
            vrow[ix[i]] = 0.f;
            atomicOr(&bm[ix[i] >> 5], 1u << (ix[i] & 31));
        }
    __syncthreads();

    // phase B: accumulate
#pragma unroll
    for (int i = 0; i < 2; i++)
        if (ix[i] >= 0 && ix[i] < QTR)
            atomicAdd(&vrow[ix[i]], wv[i]);
    __syncthreads();

    // readback: mostly register zeros; compose touched float4s from smem
    float4* orow4 = (float4*)(out + (long)r * VOC + (long)q * QTR);
    for (int i = t; i < QTR / 4; i += 256) {
        int i4 = i * 4;
        unsigned m = (bm[i4 >> 5] >> (i4 & 31)) & 0xFu;
        float4 f = make_float4(0.f, 0.f, 0.f, 0.f);
        if (m) {
            if (m & 1u) f.x = vrow[i4];
            if (m & 2u) f.y = vrow[i4 + 1];
            if (m & 4u) f.z = vrow[i4 + 2];
            if (m & 8u) f.w = vrow[i4 + 3];
        }
        __stcs(orow4 + i, f);
    }
}

// ---------------------------------------------------------------------------
extern "C" void kernel_launch(void* const* d_in, const int* in_sizes, int n_in,
                              void* d_out, int out_size)
{
    const int*   inputs = (const int*)  d_in[0];
    const float* D      = (const float*)d_in[1];
    const float* Cq     = (const float*)d_in[2];
    const float* Cc     = (const float*)d_in[3];
    const float* Mi     = (const float*)d_in[4];
    const float* E      = (const float*)d_in[5];
    const float* bq     = (const float*)d_in[6];
    const float* bc     = (const float*)d_in[7];
    const float* Wl     = (const float*)d_in[8];
    const float* bl     = (const float*)d_in[9];
    const float* We     = (const float*)d_in[10];
    const float* Wm     = (const float*)d_in[11];
    float* out = (float*)d_out;

    float *gG, *gT, *gL;
    cudaGetSymbolAddress((void**)&gG, g_G);
    cudaGetSymbolAddress((void**)&gT, g_T);
    cudaGetSymbolAddress((void**)&gL, g_log);

    static bool init = false;
    if (!init) {
        cudaFuncSetAttribute(k_G,
                             cudaFuncAttributeMaxDynamicSharedMemorySize,
                             GSMEM);
        cudaFuncSetAttribute(k_T,
                             cudaFuncAttributeMaxDynamicSharedMemorySize,
                             GSMEM);
        cudaFuncSetAttribute(k_log,
                             cudaFuncAttributeMaxDynamicSharedMemorySize,
                             GSMEM);
        init = true;
    }

    const float scale = 0.044194173824159216f;  // 512^-0.5

    // G = Wm @ We^T * scale   (full K, 64 blocks)
    k_G<<<dim3(8, 8), 256, GSMEM>>>(Wm, We, gG, scale);
    // T = M_flat @ G          (full K, 128 blocks)
    k_T<<<dim3(8, 16), 256, GSMEM>>>(Mi, gG, gT);
    // logits                  (full K, 128 blocks, single buffer)
    k_log<<<dim3(8, 4, BSZ), 256, GSMEM>>>(gT, E, gL);
    // fused lambda + softmax + bitmap scatter + streamed quarter-row write
    k_scatter<<<dim3(4, BSZ * LM), 256>>>(
        inputs, bq, bc, D, Cq, Cc, Wl, bl, gL, out);
}